// round 1
// baseline (speedup 1.0000x reference)
#include <cuda_runtime.h>

#define MEM_SIZE 262144
#define FEAT 512
#define TOPK 256
#define BATCH 128
#define CAND_CAP 8192

typedef unsigned long long u64;
typedef unsigned int u32;

// ---------------- scratch (static __device__, no allocation) ----------------
__device__ __align__(16) float g_qn[BATCH * FEAT];
__device__ float g_scores[(size_t)BATCH * MEM_SIZE];   // 128 MB
__device__ u64   g_cand[BATCH * CAND_CAP];
__device__ int   g_cand_cnt[BATCH];
__device__ int   g_topk_idx[BATCH * TOPK];

// ---------------- packed f32x2 helpers (sm_10x) ----------------
__device__ __forceinline__ u64 ffma2(u64 a, u64 b, u64 c) {
    u64 d;
    asm("fma.rn.f32x2 %0, %1, %2, %3;" : "=l"(d) : "l"(a), "l"(b), "l"(c));
    return d;
}
__device__ __forceinline__ u64 pack2(float x, float y) {
    u64 d; asm("mov.b64 %0, {%1, %2};" : "=l"(d) : "f"(x), "f"(y)); return d;
}
__device__ __forceinline__ float2 unpack2(u64 v) {
    float2 r; asm("mov.b64 {%0, %1}, %2;" : "=f"(r.x), "=f"(r.y) : "l"(v)); return r;
}

// ---------------- 1) query L2 normalize ----------------
__global__ void qnorm_kernel(const float* __restrict__ q) {
    int b = blockIdx.x;
    const float* row = q + (size_t)b * FEAT;
    float s = 0.f;
    for (int i = threadIdx.x; i < FEAT; i += blockDim.x) { float v = row[i]; s += v * v; }
    __shared__ float red[32];
    int lane = threadIdx.x & 31, wid = threadIdx.x >> 5;
    #pragma unroll
    for (int o = 16; o > 0; o >>= 1) s += __shfl_xor_sync(0xFFFFFFFFu, s, o);
    if (lane == 0) red[wid] = s;
    __syncthreads();
    if (wid == 0) {
        s = (lane < (int)(blockDim.x >> 5)) ? red[lane] : 0.f;
        #pragma unroll
        for (int o = 16; o > 0; o >>= 1) s += __shfl_xor_sync(0xFFFFFFFFu, s, o);
        if (lane == 0) red[0] = s;
    }
    __syncthreads();
    float inv = 1.0f / sqrtf(red[0]);
    for (int i = threadIdx.x; i < FEAT; i += blockDim.x)
        g_qn[(size_t)b * FEAT + i] = row[i] * inv;
}

// ---------------- 2) fp32 score GEMM: S[b][m] = q[b]·key[m] ----------------
// Tile: 128 keys x 128 batch, K-chunks of 16. 256 threads, 8x8 microtile,
// packed f32x2 FMA (2 batch lanes per 64-bit accumulator).
#define TM 128
#define TK 16
#define SPAD 4

__global__ __launch_bounds__(256, 2) void score_gemm(const float* __restrict__ sk) {
    __shared__ __align__(16) float s_a[TK][TM + SPAD];     // keys   [k][m]
    __shared__ __align__(16) float s_b[TK][BATCH + SPAD];  // query  [k][b]
    const int tid = threadIdx.x;
    const int tx = tid & 15;    // key microtile group
    const int ty = tid >> 4;    // batch microtile group
    const int m0 = blockIdx.x * TM;

    u64 acc[8][4];
    #pragma unroll
    for (int i = 0; i < 8; i++)
        #pragma unroll
        for (int j = 0; j < 4; j++) acc[i][j] = 0ull;

    for (int k0 = 0; k0 < FEAT; k0 += TK) {
        #pragma unroll
        for (int r = 0; r < 2; r++) {
            int l = tid + r * 256;            // 0..511
            int m = l >> 2;                   // 0..127
            int f4 = (l & 3) * 4;             // 0,4,8,12
            float4 va = *reinterpret_cast<const float4*>(
                sk + (size_t)(m0 + m) * FEAT + k0 + f4);
            s_a[f4 + 0][m] = va.x; s_a[f4 + 1][m] = va.y;
            s_a[f4 + 2][m] = va.z; s_a[f4 + 3][m] = va.w;
            float4 vb = *reinterpret_cast<const float4*>(
                g_qn + (size_t)m * FEAT + k0 + f4);
            s_b[f4 + 0][m] = vb.x; s_b[f4 + 1][m] = vb.y;
            s_b[f4 + 2][m] = vb.z; s_b[f4 + 3][m] = vb.w;
        }
        __syncthreads();
        #pragma unroll
        for (int k = 0; k < TK; k++) {
            float4 a0 = *reinterpret_cast<const float4*>(&s_a[k][tx * 8]);
            float4 a1 = *reinterpret_cast<const float4*>(&s_a[k][tx * 8 + 4]);
            ulonglong2 b01 = *reinterpret_cast<const ulonglong2*>(&s_b[k][ty * 8]);
            ulonglong2 b23 = *reinterpret_cast<const ulonglong2*>(&s_b[k][ty * 8 + 4]);
            float a[8] = {a0.x, a0.y, a0.z, a0.w, a1.x, a1.y, a1.z, a1.w};
            #pragma unroll
            for (int i = 0; i < 8; i++) {
                u64 aa = pack2(a[i], a[i]);
                acc[i][0] = ffma2(aa, b01.x, acc[i][0]);
                acc[i][1] = ffma2(aa, b01.y, acc[i][1]);
                acc[i][2] = ffma2(aa, b23.x, acc[i][2]);
                acc[i][3] = ffma2(aa, b23.y, acc[i][3]);
            }
        }
        __syncthreads();
    }

    // Epilogue: coalesced float4 stores, S layout [b][m]
    #pragma unroll
    for (int j = 0; j < 8; j++) {
        int bb = ty * 8 + j;
        int j2 = j >> 1;
        int hi = j & 1;
        float f[8];
        #pragma unroll
        for (int i = 0; i < 8; i++) {
            float2 t = unpack2(acc[i][j2]);
            f[i] = hi ? t.y : t.x;
        }
        float* dst = g_scores + (size_t)bb * MEM_SIZE + m0 + tx * 8;
        float4 v0 = {f[0], f[1], f[2], f[3]};
        float4 v1 = {f[4], f[5], f[6], f[7]};
        *reinterpret_cast<float4*>(dst) = v0;
        *reinterpret_cast<float4*>(dst + 4) = v1;
    }
}

// ---------------- 3) exact per-row top-256 ----------------
__device__ __forceinline__ u32 fkey(float f) {
    u32 u = __float_as_uint(f);
    return (u & 0x80000000u) ? ~u : (u | 0x80000000u);   // monotone: bigger float -> bigger uint
}

__global__ void topk_select(float* __restrict__ out_score, float* __restrict__ out_index) {
    int b = blockIdx.x;
    const float* row = g_scores + (size_t)b * MEM_SIZE;
    __shared__ u32 hist[2048];
    __shared__ int s_t;
    for (int i = threadIdx.x; i < 2048; i += blockDim.x) hist[i] = 0;
    if (threadIdx.x == 0) g_cand_cnt[b] = 0;
    __syncthreads();

    int lane = threadIdx.x & 31;
    // Pass 1: 11-bit histogram (warp-aggregated atomics)
    for (int i = threadIdx.x; i < MEM_SIZE; i += blockDim.x) {
        u32 bin = fkey(row[i]) >> 21;
        u32 mask = __match_any_sync(0xFFFFFFFFu, bin);
        int leader = __ffs(mask) - 1;
        if (lane == leader) atomicAdd(&hist[bin], __popc(mask));
    }
    __syncthreads();
    if (threadIdx.x == 0) {
        u32 cum = 0; int t = 0;
        for (int bin = 2047; bin >= 0; bin--) {
            cum += hist[bin];
            if (cum >= TOPK) { t = bin; break; }
        }
        s_t = t;
    }
    __syncthreads();
    u32 t = (u32)s_t;

    // Pass 2: collect candidates with bin >= threshold bin
    for (int i = threadIdx.x; i < MEM_SIZE; i += blockDim.x) {
        u32 u = fkey(row[i]);
        if ((u >> 21) >= t) {
            int p = atomicAdd(&g_cand_cnt[b], 1);
            if (p < CAND_CAP)
                g_cand[(size_t)b * CAND_CAP + p] =
                    ((u64)u << 32) | (u32)(0xFFFFFFFFu - (u32)i);  // tie-break: smaller idx wins
        }
    }
    __syncthreads();

    int n = g_cand_cnt[b];
    if (n > CAND_CAP) n = CAND_CAP;
    const u64* cand = g_cand + (size_t)b * CAND_CAP;
    // Exact rank (keys unique because index is embedded)
    for (int c = threadIdx.x; c < n; c += blockDim.x) {
        u64 kc = cand[c];
        int rank = 0;
        for (int j = 0; j < n; j++) rank += (cand[j] > kc);
        if (rank < TOPK) {
            int idx = (int)(0xFFFFFFFFu - (u32)(kc & 0xFFFFFFFFull));
            out_score[b * TOPK + rank] = row[idx];
            out_index[b * TOPK + rank] = (float)idx;
            g_topk_idx[b * TOPK + rank] = idx;
        }
    }
}

// ---------------- 4) gather color_value rows ----------------
__global__ void gather_kernel(const float* __restrict__ cv, float* __restrict__ out_feat) {
    int r = blockIdx.x;                       // 0 .. BATCH*TOPK-1
    int idx = g_topk_idx[r];
    const float4* src = reinterpret_cast<const float4*>(cv + (size_t)idx * FEAT);
    float4* dst = reinterpret_cast<float4*>(out_feat + (size_t)r * FEAT);
    dst[threadIdx.x] = src[threadIdx.x];      // 128 threads x float4 = 512 floats
}

// ---------------- launch ----------------
extern "C" void kernel_launch(void* const* d_in, const int* in_sizes, int n_in,
                              void* d_out, int out_size) {
    const float* query = (const float*)d_in[0];   // [128, 512]
    const float* skey  = (const float*)d_in[1];   // [262144, 512]
    const float* cval  = (const float*)d_in[2];   // [262144, 512]
    float* out = (float*)d_out;
    float* out_feat  = out;                                   // [128,256,512]
    float* out_score = out + (size_t)BATCH * TOPK * FEAT;     // [128,256]
    float* out_index = out_score + (size_t)BATCH * TOPK;      // [128,256] as float

    qnorm_kernel<<<BATCH, 128>>>(query);
    score_gemm<<<MEM_SIZE / TM, 256>>>(skey);
    topk_select<<<BATCH, 1024>>>(out_score, out_index);
    gather_kernel<<<BATCH * TOPK, 128>>>(cval, out_feat);
}

// round 5
// speedup vs baseline: 1.8983x; 1.8983x over previous
#include <cuda_runtime.h>
#include <cuda_bf16.h>
#include <cstdint>

#define MEM_SIZE 262144
#define FEAT 512
#define TOPK 256
#define BATCH 128
#define CAND_CAP 4096

typedef unsigned long long u64;
typedef unsigned int u32;

// ---------------- scratch (static __device__, no allocation) ----------------
__device__ __align__(16) float g_qn[BATCH * FEAT];
__device__ __align__(16) __nv_bfloat16 g_qbf[BATCH * FEAT];
__device__ float g_scores[(size_t)BATCH * MEM_SIZE];   // approx (bf16-mma) scores
__device__ int   g_cand_idx[BATCH * CAND_CAP];
__device__ int   g_cand_cnt[BATCH];
__device__ int   g_topk_idx[BATCH * TOPK];

// ---------------- helpers ----------------
__device__ __forceinline__ uint32_t smem_u32(const void* p) {
    uint32_t a;
    asm("{ .reg .u64 t; cvta.to.shared.u64 t, %1; cvt.u32.u64 %0, t; }" : "=r"(a) : "l"(p));
    return a;
}
__device__ __forceinline__ u32 f2bf2(float lo, float hi) {
    u32 r; asm("cvt.rn.bf16x2.f32 %0, %1, %2;" : "=r"(r) : "f"(hi), "f"(lo)); return r;
}
__device__ __forceinline__ u32 swz(u32 off) { return off ^ ((off >> 3) & 0x70u); }

__device__ __forceinline__ void ldsm_x4(u32* r, u32 addr) {
    asm volatile("ldmatrix.sync.aligned.m8n8.x4.shared.b16 {%0,%1,%2,%3}, [%4];"
                 : "=r"(r[0]), "=r"(r[1]), "=r"(r[2]), "=r"(r[3]) : "r"(addr));
}
__device__ __forceinline__ void mma16816(float* c, const u32* a, u32 b0, u32 b1) {
    asm volatile(
        "mma.sync.aligned.m16n8k16.row.col.f32.bf16.bf16.f32 "
        "{%0,%1,%2,%3}, {%4,%5,%6,%7}, {%8,%9}, {%0,%1,%2,%3};"
        : "+f"(c[0]), "+f"(c[1]), "+f"(c[2]), "+f"(c[3])
        : "r"(a[0]), "r"(a[1]), "r"(a[2]), "r"(a[3]), "r"(b0), "r"(b1));
}
__device__ __forceinline__ void cp_async16(u32 dst, const void* src) {
    u64 g = (u64)__cvta_generic_to_global(src);
    asm volatile("cp.async.cg.shared.global [%0], [%1], 16;" :: "r"(dst), "l"(g) : "memory");
}
#define CP_COMMIT() asm volatile("cp.async.commit_group;" ::: "memory")
#define CP_WAIT0()  asm volatile("cp.async.wait_group 0;" ::: "memory")

// ---------------- 1) query L2 normalize + bf16 copy ----------------
__global__ void qnorm_kernel(const float* __restrict__ q) {
    int b = blockIdx.x;
    const float* row = q + (size_t)b * FEAT;
    float s = 0.f;
    for (int i = threadIdx.x; i < FEAT; i += blockDim.x) { float v = row[i]; s += v * v; }
    __shared__ float red[32];
    int lane = threadIdx.x & 31, wid = threadIdx.x >> 5;
    #pragma unroll
    for (int o = 16; o > 0; o >>= 1) s += __shfl_xor_sync(0xFFFFFFFFu, s, o);
    if (lane == 0) red[wid] = s;
    __syncthreads();
    if (wid == 0) {
        s = (lane < (int)(blockDim.x >> 5)) ? red[lane] : 0.f;
        #pragma unroll
        for (int o = 16; o > 0; o >>= 1) s += __shfl_xor_sync(0xFFFFFFFFu, s, o);
        if (lane == 0) red[0] = s;
    }
    __syncthreads();
    float inv = 1.0f / sqrtf(red[0]);
    for (int i = threadIdx.x; i < FEAT; i += blockDim.x) {
        float v = row[i] * inv;
        g_qn[(size_t)b * FEAT + i] = v;
        g_qbf[(size_t)b * FEAT + i] = __float2bfloat16(v);
    }
}

// ---------------- 2) bf16 mma.sync score GEMM ----------------
// C[128 batch, MEM keys]; block tile 128x128, K = 8 chunks of 64.
// A (queries) fully resident in SMEM (8 x 16KB); B double-buffered (2 x 16KB).
#define BK 64
#define NCH 8
#define A_CHUNK 16384
#define B_TILE 16384
#define SM_B (NCH * A_CHUNK)                  // 131072
#define GEMM_SMEM (SM_B + 2 * B_TILE)         // 163840

__global__ __launch_bounds__(256) void score_gemm_mma(const float* __restrict__ sk) {
    extern __shared__ __align__(1024) char smem[];
    const int tid = threadIdx.x;
    const int wid = tid >> 5, lane = tid & 31;
    const int wm = (wid & 1) * 64;          // warp M offset (batch rows)
    const int wn = (wid >> 1) * 32;         // warp N offset (keys)
    const int n0 = blockIdx.x * 128;
    const u32 sbase = smem_u32(smem);

    float acc[4][4][4];
    #pragma unroll
    for (int i = 0; i < 4; i++)
        #pragma unroll
        for (int j = 0; j < 4; j++)
            #pragma unroll
            for (int k = 0; k < 4; k++) acc[i][j][k] = 0.f;

    // ---- load ALL of A (128 rows x 512 bf16, 8 swizzled chunks) via cp.async ----
    {
        const char* src0 = reinterpret_cast<const char*>(g_qbf);
        #pragma unroll
        for (int it = 0; it < 32; it++) {
            int id = tid + it * 256;          // 0..8191 granules of 16B
            int c = id >> 10;                 // chunk 0..7
            int r = (id >> 3) & 127;          // row 0..127
            int g = id & 7;                   // 16B granule in row
            cp_async16(sbase + c * A_CHUNK + swz(r * 128 + g * 16),
                       src0 + r * 1024 + c * 128 + g * 16);
        }
        CP_COMMIT();
    }

    float4 st[4][2];   // B fp32 staging for one chunk
    auto ldgB = [&](int c) {
        #pragma unroll
        for (int it = 0; it < 4; it++) {
            int id = tid + it * 256;        // 0..1023
            int r = id >> 3, c32 = id & 7;  // 128 key rows x 8 (8-float groups)
            const float4* p = reinterpret_cast<const float4*>(
                sk + (size_t)(n0 + r) * FEAT + c * BK + c32 * 8);
            st[it][0] = p[0]; st[it][1] = p[1];
        }
    };
    auto stsB = [&](int buf) {
        char* bb = smem + SM_B + buf * B_TILE;
        #pragma unroll
        for (int it = 0; it < 4; it++) {
            int id = tid + it * 256;
            int r = id >> 3, c32 = id & 7;
            uint4 o;
            o.x = f2bf2(st[it][0].x, st[it][0].y);
            o.y = f2bf2(st[it][0].z, st[it][0].w);
            o.z = f2bf2(st[it][1].x, st[it][1].y);
            o.w = f2bf2(st[it][1].z, st[it][1].w);
            *reinterpret_cast<uint4*>(bb + swz(r * 128 + c32 * 16)) = o;
        }
    };

    const int jj = lane >> 3;
    const int akoff = (jj >= 2) ? 16 : 0;
    const int amoff = (jj & 1) * 8;
    const int bnoff = (jj >= 2) ? 8 : 0;
    const int bkoff = (jj & 1) * 16;
    auto compute = [&](int c, int buf) {
        u32 abase = sbase + c * A_CHUNK;
        u32 bbase = sbase + SM_B + buf * B_TILE;
        #pragma unroll
        for (int ks = 0; ks < 4; ks++) {
            u32 a[4][4], b[2][4];
            #pragma unroll
            for (int mt = 0; mt < 4; mt++) {
                int arow = wm + mt * 16 + amoff + (lane & 7);
                ldsm_x4(a[mt], abase + arow * 128 + ((ks * 32 + akoff) ^ ((arow & 7) * 16)));
            }
            #pragma unroll
            for (int nt2 = 0; nt2 < 2; nt2++) {
                int brow = wn + nt2 * 16 + bnoff + (lane & 7);
                ldsm_x4(b[nt2], bbase + brow * 128 + ((ks * 32 + bkoff) ^ ((brow & 7) * 16)));
            }
            #pragma unroll
            for (int mt = 0; mt < 4; mt++)
                #pragma unroll
                for (int nt = 0; nt < 4; nt++)
                    mma16816(acc[mt][nt], a[mt], b[nt >> 1][(nt & 1) * 2],
                             b[nt >> 1][(nt & 1) * 2 + 1]);
        }
    };

    // ---- pipeline: B double buffer, one barrier per chunk ----
    ldgB(0);
    CP_WAIT0();          // A resident
    stsB(0);
    __syncthreads();
    for (int c = 0; c < NCH; c++) {
        int cur = c & 1;
        if (c < NCH - 1) ldgB(c + 1);
        compute(c, cur);
        if (c < NCH - 1) stsB(cur ^ 1);
        __syncthreads();
    }

    // ---- epilogue ----
    #pragma unroll
    for (int mt = 0; mt < 4; mt++) {
        int r0 = wm + mt * 16 + (lane >> 2);
        #pragma unroll
        for (int nt = 0; nt < 4; nt++) {
            int col = n0 + wn + nt * 8 + (lane & 3) * 2;
            float2 v0 = {acc[mt][nt][0], acc[mt][nt][1]};
            float2 v1 = {acc[mt][nt][2], acc[mt][nt][3]};
            *reinterpret_cast<float2*>(g_scores + (size_t)r0 * MEM_SIZE + col) = v0;
            *reinterpret_cast<float2*>(g_scores + (size_t)(r0 + 8) * MEM_SIZE + col) = v1;
        }
    }
}

// ---------------- 3) candidate select on approx scores ----------------
__device__ __forceinline__ u32 fkey(float f) {
    u32 u = __float_as_uint(f);
    return (u & 0x80000000u) ? ~u : (u | 0x80000000u);
}

__global__ void cand_select() {
    int b = blockIdx.x;
    const float* row = g_scores + (size_t)b * MEM_SIZE;
    __shared__ u32 hist[2048];
    __shared__ float s_thresh;
    for (int i = threadIdx.x; i < 2048; i += blockDim.x) hist[i] = 0;
    if (threadIdx.x == 0) g_cand_cnt[b] = 0;
    __syncthreads();

    int lane = threadIdx.x & 31;
    for (int i = threadIdx.x; i < MEM_SIZE; i += blockDim.x) {
        u32 bin = fkey(row[i]) >> 21;
        u32 mask = __match_any_sync(0xFFFFFFFFu, bin);
        if (lane == (__ffs(mask) - 1)) atomicAdd(&hist[bin], __popc(mask));
    }
    __syncthreads();
    if (threadIdx.x == 0) {
        u32 cum = 0; int t = 0;
        for (int bin = 2047; bin >= 0; bin--) {
            cum += hist[bin];
            if (cum >= TOPK) { t = bin; break; }
        }
        u32 k = (u32)t << 21;
        float edge = (k & 0x80000000u) ? __uint_as_float(k ^ 0x80000000u)
                                       : __uint_as_float(~k);
        s_thresh = edge - 2.0e-3f;   // ~57 sigma of bf16-mma noise
    }
    __syncthreads();
    float th = s_thresh;
    for (int i = threadIdx.x; i < MEM_SIZE; i += blockDim.x) {
        if (row[i] > th) {
            int p = atomicAdd(&g_cand_cnt[b], 1);
            if (p < CAND_CAP) g_cand_idx[b * CAND_CAP + p] = i;
        }
    }
}

// ---------------- 4) exact fp32 rescore (sequential-k order!) + exact rank ----
// CRITICAL: the dot product MUST accumulate in pure ascending-k order with a
// single fp32 fma chain — this exact order matched the reference's ordering in
// R1 (zero index flips). Do not parallelize the reduction.
#define RES_SMEM (CAND_CAP * 8 + CAND_CAP * 4 + FEAT * 4)   // 51200 B

__global__ __launch_bounds__(1024) void rescore_rank(const float* __restrict__ sk,
                                                     float* __restrict__ out_score,
                                                     float* __restrict__ out_index) {
    int b = blockIdx.x;
    extern __shared__ __align__(16) char rsm[];
    u64*   s_key = reinterpret_cast<u64*>(rsm);
    float* s_sc  = reinterpret_cast<float*>(rsm + CAND_CAP * 8);
    float* s_q   = reinterpret_cast<float*>(rsm + CAND_CAP * 12);
    for (int i = threadIdx.x; i < FEAT; i += blockDim.x) s_q[i] = g_qn[(size_t)b * FEAT + i];
    __syncthreads();

    int n = g_cand_cnt[b];
    if (n > CAND_CAP) n = CAND_CAP;
    const float4* q4 = reinterpret_cast<const float4*>(s_q);
    for (int ci = threadIdx.x; ci < n; ci += blockDim.x) {
        int idx = g_cand_idx[b * CAND_CAP + ci];
        const float4* kr = reinterpret_cast<const float4*>(sk + (size_t)idx * FEAT);
        float acc = 0.f;
        #pragma unroll 8
        for (int j = 0; j < FEAT / 4; j++) {
            float4 kv = kr[j];
            float4 qv = q4[j];
            acc = fmaf(qv.x, kv.x, acc);
            acc = fmaf(qv.y, kv.y, acc);
            acc = fmaf(qv.z, kv.z, acc);
            acc = fmaf(qv.w, kv.w, acc);
        }
        s_sc[ci] = acc;
        s_key[ci] = ((u64)fkey(acc) << 32) | (u32)(0xFFFFFFFFu - (u32)idx);
    }
    __syncthreads();
    for (int ci = threadIdx.x; ci < n; ci += blockDim.x) {
        u64 kc = s_key[ci];
        int rank = 0;
        for (int j = 0; j < n; j++) rank += (s_key[j] > kc);
        if (rank < TOPK) {
            int idx = (int)(0xFFFFFFFFu - (u32)(kc & 0xFFFFFFFFull));
            out_score[b * TOPK + rank] = s_sc[ci];
            out_index[b * TOPK + rank] = (float)idx;
            g_topk_idx[b * TOPK + rank] = idx;
        }
    }
}

// ---------------- 5) gather ----------------
__global__ void gather_kernel(const float* __restrict__ cv, float* __restrict__ out_feat) {
    int r = blockIdx.x;
    int idx = g_topk_idx[r];
    const float4* src = reinterpret_cast<const float4*>(cv + (size_t)idx * FEAT);
    float4* dst = reinterpret_cast<float4*>(out_feat + (size_t)r * FEAT);
    dst[threadIdx.x] = src[threadIdx.x];
}

// ---------------- launch ----------------
extern "C" void kernel_launch(void* const* d_in, const int* in_sizes, int n_in,
                              void* d_out, int out_size) {
    const float* query = (const float*)d_in[0];
    const float* skey  = (const float*)d_in[1];
    const float* cval  = (const float*)d_in[2];
    float* out = (float*)d_out;
    float* out_feat  = out;
    float* out_score = out + (size_t)BATCH * TOPK * FEAT;
    float* out_index = out_score + (size_t)BATCH * TOPK;

    cudaFuncSetAttribute(score_gemm_mma, cudaFuncAttributeMaxDynamicSharedMemorySize, GEMM_SMEM);
    cudaFuncSetAttribute(rescore_rank, cudaFuncAttributeMaxDynamicSharedMemorySize, RES_SMEM);

    qnorm_kernel<<<BATCH, 128>>>(query);
    score_gemm_mma<<<MEM_SIZE / 128, 256, GEMM_SMEM>>>(skey);
    cand_select<<<BATCH, 1024>>>();
    rescore_rank<<<BATCH, 1024, RES_SMEM>>>(skey, out_score, out_index);
    gather_kernel<<<BATCH * TOPK, 128>>>(cval, out_feat);
}

// round 6
// speedup vs baseline: 1.9995x; 1.0533x over previous
#include <cuda_runtime.h>
#include <cuda_bf16.h>
#include <cstdint>

#define MEM_SIZE 262144
#define FEAT 512
#define TOPK 256
#define BATCH 128
#define CAND_CAP 4096

typedef unsigned long long u64;
typedef unsigned int u32;

// ---------------- scratch (static __device__, no allocation) ----------------
__device__ __align__(16) float g_qn[BATCH * FEAT];
__device__ __align__(16) __nv_bfloat16 g_qbf[BATCH * FEAT];
__device__ float g_scores[(size_t)BATCH * MEM_SIZE];   // approx (bf16-mma) scores
__device__ int   g_cand_idx[BATCH * CAND_CAP];
__device__ int   g_cand_cnt[BATCH];
__device__ int   g_topk_idx[BATCH * TOPK];

// ---------------- helpers ----------------
__device__ __forceinline__ uint32_t smem_u32(const void* p) {
    uint32_t a;
    asm("{ .reg .u64 t; cvta.to.shared.u64 t, %1; cvt.u32.u64 %0, t; }" : "=r"(a) : "l"(p));
    return a;
}
__device__ __forceinline__ u32 f2bf2(float lo, float hi) {
    u32 r; asm("cvt.rn.bf16x2.f32 %0, %1, %2;" : "=r"(r) : "f"(hi), "f"(lo)); return r;
}
__device__ __forceinline__ u32 swz(u32 off) { return off ^ ((off >> 3) & 0x70u); }

__device__ __forceinline__ void ldsm_x4(u32* r, u32 addr) {
    asm volatile("ldmatrix.sync.aligned.m8n8.x4.shared.b16 {%0,%1,%2,%3}, [%4];"
                 : "=r"(r[0]), "=r"(r[1]), "=r"(r[2]), "=r"(r[3]) : "r"(addr));
}
__device__ __forceinline__ void mma16816(float* c, const u32* a, u32 b0, u32 b1) {
    asm volatile(
        "mma.sync.aligned.m16n8k16.row.col.f32.bf16.bf16.f32 "
        "{%0,%1,%2,%3}, {%4,%5,%6,%7}, {%8,%9}, {%0,%1,%2,%3};"
        : "+f"(c[0]), "+f"(c[1]), "+f"(c[2]), "+f"(c[3])
        : "r"(a[0]), "r"(a[1]), "r"(a[2]), "r"(a[3]), "r"(b0), "r"(b1));
}
__device__ __forceinline__ void cp_async16(u32 dst, const void* src) {
    u64 g = (u64)__cvta_generic_to_global(src);
    asm volatile("cp.async.cg.shared.global [%0], [%1], 16;" :: "r"(dst), "l"(g) : "memory");
}
#define CP_COMMIT() asm volatile("cp.async.commit_group;" ::: "memory")
#define CP_WAIT0()  asm volatile("cp.async.wait_group 0;" ::: "memory")

// ---------------- 1) query L2 normalize + bf16 copy ----------------
__global__ void qnorm_kernel(const float* __restrict__ q) {
    int b = blockIdx.x;
    const float* row = q + (size_t)b * FEAT;
    float s = 0.f;
    for (int i = threadIdx.x; i < FEAT; i += blockDim.x) { float v = row[i]; s += v * v; }
    __shared__ float red[32];
    int lane = threadIdx.x & 31, wid = threadIdx.x >> 5;
    #pragma unroll
    for (int o = 16; o > 0; o >>= 1) s += __shfl_xor_sync(0xFFFFFFFFu, s, o);
    if (lane == 0) red[wid] = s;
    __syncthreads();
    if (wid == 0) {
        s = (lane < (int)(blockDim.x >> 5)) ? red[lane] : 0.f;
        #pragma unroll
        for (int o = 16; o > 0; o >>= 1) s += __shfl_xor_sync(0xFFFFFFFFu, s, o);
        if (lane == 0) red[0] = s;
    }
    __syncthreads();
    float inv = 1.0f / sqrtf(red[0]);
    for (int i = threadIdx.x; i < FEAT; i += blockDim.x) {
        float v = row[i] * inv;
        g_qn[(size_t)b * FEAT + i] = v;
        g_qbf[(size_t)b * FEAT + i] = __float2bfloat16(v);
    }
}

// ---------------- 2) bf16 mma.sync score GEMM ----------------
// C[128 batch, MEM keys]; block tile 128x128, K chunks of 64, both A and B
// double-buffered (4 x 16KB = 64KB smem) -> 2 CTAs/SM, 16 warps/SM.
#define BK 64
#define A_TILE 16384               // 128 rows * 128 B
#define B_TILE 16384
#define GEMM_SMEM (2 * A_TILE + 2 * B_TILE)   // 64 KB

__global__ __launch_bounds__(256, 2) void score_gemm_mma(const float* __restrict__ sk) {
    extern __shared__ __align__(1024) char smem[];
    const int tid = threadIdx.x;
    const int wid = tid >> 5, lane = tid & 31;
    const int wm = (wid & 1) * 64;          // warp M offset (batch rows)
    const int wn = (wid >> 1) * 32;         // warp N offset (keys)
    const int n0 = blockIdx.x * 128;
    const u32 sbase = smem_u32(smem);

    float acc[4][4][4];
    #pragma unroll
    for (int i = 0; i < 4; i++)
        #pragma unroll
        for (int j = 0; j < 4; j++)
            #pragma unroll
            for (int k = 0; k < 4; k++) acc[i][j][k] = 0.f;

    float4 st[4][2];   // B fp32 staging (one chunk)

    auto ldgB = [&](int c) {
        #pragma unroll
        for (int it = 0; it < 4; it++) {
            int id = tid + it * 256;        // 0..1023
            int r = id >> 3, c32 = id & 7;  // 128 key rows x 8 (8-float groups)
            const float4* p = reinterpret_cast<const float4*>(
                sk + (size_t)(n0 + r) * FEAT + c * BK + c32 * 8);
            st[it][0] = p[0]; st[it][1] = p[1];
        }
    };
    auto stsB = [&](int buf) {
        char* bb = smem + 2 * A_TILE + buf * B_TILE;
        #pragma unroll
        for (int it = 0; it < 4; it++) {
            int id = tid + it * 256;
            int r = id >> 3, c32 = id & 7;
            uint4 o;
            o.x = f2bf2(st[it][0].x, st[it][0].y);
            o.y = f2bf2(st[it][0].z, st[it][0].w);
            o.z = f2bf2(st[it][1].x, st[it][1].y);
            o.w = f2bf2(st[it][1].z, st[it][1].w);
            *reinterpret_cast<uint4*>(bb + swz(r * 128 + c32 * 16)) = o;
        }
    };
    auto cpA = [&](int c, int buf) {
        const char* src0 = reinterpret_cast<const char*>(g_qbf);
        u32 dst0 = sbase + buf * A_TILE;
        #pragma unroll
        for (int it = 0; it < 4; it++) {
            int id = tid + it * 256;        // 0..1023: 128 rows x 8 granules
            int r = id >> 3, c16 = id & 7;
            cp_async16(dst0 + swz(r * 128 + c16 * 16),
                       src0 + r * 1024 + c * 128 + c16 * 16);
        }
    };

    const int jj = lane >> 3;
    const int akoff = (jj >= 2) ? 16 : 0;     // A tiles: (0,0),(8,0),(0,8),(8,8)
    const int amoff = (jj & 1) * 8;
    const int bnoff = (jj >= 2) ? 8 : 0;      // B tiles: (n0,k0),(n0,k8),(n8,k0),(n8,k8)
    const int bkoff = (jj & 1) * 16;
    auto compute = [&](int buf) {
        u32 abase = sbase + buf * A_TILE;
        u32 bbase = sbase + 2 * A_TILE + buf * B_TILE;
        #pragma unroll
        for (int ks = 0; ks < 4; ks++) {
            u32 a[4][4], b[2][4];
            #pragma unroll
            for (int mt = 0; mt < 4; mt++) {
                int arow = wm + mt * 16 + amoff + (lane & 7);
                ldsm_x4(a[mt], abase + arow * 128 + ((ks * 32 + akoff) ^ ((arow & 7) * 16)));
            }
            #pragma unroll
            for (int nt2 = 0; nt2 < 2; nt2++) {
                int brow = wn + nt2 * 16 + bnoff + (lane & 7);
                ldsm_x4(b[nt2], bbase + brow * 128 + ((ks * 32 + bkoff) ^ ((brow & 7) * 16)));
            }
            #pragma unroll
            for (int mt = 0; mt < 4; mt++)
                #pragma unroll
                for (int nt = 0; nt < 4; nt++)
                    mma16816(acc[mt][nt], a[mt], b[nt >> 1][(nt & 1) * 2],
                             b[nt >> 1][(nt & 1) * 2 + 1]);
        }
    };

    // ---- pipeline ----
    ldgB(0);
    cpA(0, 0);
    CP_COMMIT();
    CP_WAIT0();
    stsB(0);
    __syncthreads();
    for (int c = 0; c < FEAT / BK; c++) {
        int cur = c & 1;
        if (c < FEAT / BK - 1) { ldgB(c + 1); cpA(c + 1, cur ^ 1); CP_COMMIT(); }
        compute(cur);
        if (c < FEAT / BK - 1) { CP_WAIT0(); stsB(cur ^ 1); }
        __syncthreads();
    }

    // ---- epilogue ----
    #pragma unroll
    for (int mt = 0; mt < 4; mt++) {
        int r0 = wm + mt * 16 + (lane >> 2);
        #pragma unroll
        for (int nt = 0; nt < 4; nt++) {
            int col = n0 + wn + nt * 8 + (lane & 3) * 2;
            float2 v0 = {acc[mt][nt][0], acc[mt][nt][1]};
            float2 v1 = {acc[mt][nt][2], acc[mt][nt][3]};
            *reinterpret_cast<float2*>(g_scores + (size_t)r0 * MEM_SIZE + col) = v0;
            *reinterpret_cast<float2*>(g_scores + (size_t)(r0 + 8) * MEM_SIZE + col) = v1;
        }
    }
}

// ---------------- 3) candidate select on approx scores ----------------
__device__ __forceinline__ u32 fkey(float f) {
    u32 u = __float_as_uint(f);
    return (u & 0x80000000u) ? ~u : (u | 0x80000000u);
}

__global__ void cand_select() {
    int b = blockIdx.x;
    const float* row = g_scores + (size_t)b * MEM_SIZE;
    __shared__ u32 hist[2048];
    __shared__ float s_thresh;
    for (int i = threadIdx.x; i < 2048; i += blockDim.x) hist[i] = 0;
    if (threadIdx.x == 0) g_cand_cnt[b] = 0;
    __syncthreads();

    int lane = threadIdx.x & 31;
    for (int i = threadIdx.x; i < MEM_SIZE; i += blockDim.x) {
        u32 bin = fkey(row[i]) >> 21;
        u32 mask = __match_any_sync(0xFFFFFFFFu, bin);
        if (lane == (__ffs(mask) - 1)) atomicAdd(&hist[bin], __popc(mask));
    }
    __syncthreads();
    if (threadIdx.x == 0) {
        u32 cum = 0; int t = 0;
        for (int bin = 2047; bin >= 0; bin--) {
            cum += hist[bin];
            if (cum >= TOPK) { t = bin; break; }
        }
        u32 k = (u32)t << 21;
        float edge = (k & 0x80000000u) ? __uint_as_float(k ^ 0x80000000u)
                                       : __uint_as_float(~k);
        s_thresh = edge - 2.0e-3f;   // ~57 sigma of bf16-mma noise
    }
    __syncthreads();
    float th = s_thresh;
    for (int i = threadIdx.x; i < MEM_SIZE; i += blockDim.x) {
        if (row[i] > th) {
            int p = atomicAdd(&g_cand_cnt[b], 1);
            if (p < CAND_CAP) g_cand_idx[b * CAND_CAP + p] = i;
        }
    }
}

// ---------------- 4) exact fp32 rescore (sequential-k order!) + exact rank ----
// CRITICAL: the dot product MUST accumulate in pure ascending-k order with a
// single fp32 fma chain — this exact order matches the reference ordering
// (R1/R5 passed with it). Do not parallelize the reduction.
#define RES_SMEM (CAND_CAP * 8 + CAND_CAP * 4 + FEAT * 4)   // 51200 B

__global__ __launch_bounds__(1024) void rescore_rank(const float* __restrict__ sk,
                                                     float* __restrict__ out_score,
                                                     float* __restrict__ out_index) {
    int b = blockIdx.x;
    extern __shared__ __align__(16) char rsm[];
    u64*   s_key = reinterpret_cast<u64*>(rsm);
    float* s_sc  = reinterpret_cast<float*>(rsm + CAND_CAP * 8);
    float* s_q   = reinterpret_cast<float*>(rsm + CAND_CAP * 12);
    for (int i = threadIdx.x; i < FEAT; i += blockDim.x) s_q[i] = g_qn[(size_t)b * FEAT + i];
    __syncthreads();

    int n = g_cand_cnt[b];
    if (n > CAND_CAP) n = CAND_CAP;
    const float4* q4 = reinterpret_cast<const float4*>(s_q);
    for (int ci = threadIdx.x; ci < n; ci += blockDim.x) {
        int idx = g_cand_idx[b * CAND_CAP + ci];
        const float4* kr = reinterpret_cast<const float4*>(sk + (size_t)idx * FEAT);
        float acc = 0.f;
        #pragma unroll 8
        for (int j = 0; j < FEAT / 4; j++) {
            float4 kv = kr[j];
            float4 qv = q4[j];
            acc = fmaf(qv.x, kv.x, acc);
            acc = fmaf(qv.y, kv.y, acc);
            acc = fmaf(qv.z, kv.z, acc);
            acc = fmaf(qv.w, kv.w, acc);
        }
        s_sc[ci] = acc;
        s_key[ci] = ((u64)fkey(acc) << 32) | (u32)(0xFFFFFFFFu - (u32)idx);
    }
    __syncthreads();
    for (int ci = threadIdx.x; ci < n; ci += blockDim.x) {
        u64 kc = s_key[ci];
        int rank = 0;
        for (int j = 0; j < n; j++) rank += (s_key[j] > kc);
        if (rank < TOPK) {
            int idx = (int)(0xFFFFFFFFu - (u32)(kc & 0xFFFFFFFFull));
            out_score[b * TOPK + rank] = s_sc[ci];
            out_index[b * TOPK + rank] = (float)idx;
            g_topk_idx[b * TOPK + rank] = idx;
        }
    }
}

// ---------------- 5) gather ----------------
__global__ void gather_kernel(const float* __restrict__ cv, float* __restrict__ out_feat) {
    int r = blockIdx.x;
    int idx = g_topk_idx[r];
    const float4* src = reinterpret_cast<const float4*>(cv + (size_t)idx * FEAT);
    float4* dst = reinterpret_cast<float4*>(out_feat + (size_t)r * FEAT);
    dst[threadIdx.x] = src[threadIdx.x];
}

// ---------------- launch ----------------
extern "C" void kernel_launch(void* const* d_in, const int* in_sizes, int n_in,
                              void* d_out, int out_size) {
    const float* query = (const float*)d_in[0];
    const float* skey  = (const float*)d_in[1];
    const float* cval  = (const float*)d_in[2];
    float* out = (float*)d_out;
    float* out_feat  = out;
    float* out_score = out + (size_t)BATCH * TOPK * FEAT;
    float* out_index = out_score + (size_t)BATCH * TOPK;

    cudaFuncSetAttribute(score_gemm_mma, cudaFuncAttributeMaxDynamicSharedMemorySize, GEMM_SMEM);
    cudaFuncSetAttribute(rescore_rank, cudaFuncAttributeMaxDynamicSharedMemorySize, RES_SMEM);

    qnorm_kernel<<<BATCH, 128>>>(query);
    score_gemm_mma<<<MEM_SIZE / 128, 256, GEMM_SMEM>>>(skey);
    cand_select<<<BATCH, 1024>>>();
    rescore_rank<<<BATCH, 1024, RES_SMEM>>>(skey, out_score, out_index);
    gather_kernel<<<BATCH * TOPK, 128>>>(cval, out_feat);
}

// round 7
// speedup vs baseline: 3.6055x; 1.8032x over previous
#include <cuda_runtime.h>
#include <cuda_bf16.h>
#include <cstdint>

#define MEM_SIZE 262144
#define FEAT 512
#define TOPK 256
#define BATCH 128
#define CAND_CAP 4096

typedef unsigned long long u64;
typedef unsigned int u32;

// ---------------- scratch (static __device__, no allocation) ----------------
__device__ __align__(16) float g_qn[BATCH * FEAT];
__device__ __align__(16) __nv_bfloat16 g_qbf[BATCH * FEAT];
__device__ __align__(16) __nv_bfloat16 g_sbf[(size_t)BATCH * MEM_SIZE];  // approx scores, bf16, 64 MB
__device__ int   g_cand_idx[BATCH * CAND_CAP];
__device__ int   g_cand_cnt[BATCH];
__device__ int   g_topk_idx[BATCH * TOPK];

// ---------------- helpers ----------------
__device__ __forceinline__ uint32_t smem_u32(const void* p) {
    uint32_t a;
    asm("{ .reg .u64 t; cvta.to.shared.u64 t, %1; cvt.u32.u64 %0, t; }" : "=r"(a) : "l"(p));
    return a;
}
__device__ __forceinline__ u32 f2bf2(float lo, float hi) {
    u32 r; asm("cvt.rn.bf16x2.f32 %0, %1, %2;" : "=r"(r) : "f"(hi), "f"(lo)); return r;
}
__device__ __forceinline__ u32 swz(u32 off) { return off ^ ((off >> 3) & 0x70u); }

__device__ __forceinline__ void ldsm_x4(u32* r, u32 addr) {
    asm volatile("ldmatrix.sync.aligned.m8n8.x4.shared.b16 {%0,%1,%2,%3}, [%4];"
                 : "=r"(r[0]), "=r"(r[1]), "=r"(r[2]), "=r"(r[3]) : "r"(addr));
}
__device__ __forceinline__ void mma16816(float* c, const u32* a, u32 b0, u32 b1) {
    asm volatile(
        "mma.sync.aligned.m16n8k16.row.col.f32.bf16.bf16.f32 "
        "{%0,%1,%2,%3}, {%4,%5,%6,%7}, {%8,%9}, {%0,%1,%2,%3};"
        : "+f"(c[0]), "+f"(c[1]), "+f"(c[2]), "+f"(c[3])
        : "r"(a[0]), "r"(a[1]), "r"(a[2]), "r"(a[3]), "r"(b0), "r"(b1));
}
__device__ __forceinline__ void cp_async16(u32 dst, const void* src) {
    u64 g = (u64)__cvta_generic_to_global(src);
    asm volatile("cp.async.cg.shared.global [%0], [%1], 16;" :: "r"(dst), "l"(g) : "memory");
}
#define CP_COMMIT() asm volatile("cp.async.commit_group;" ::: "memory")
#define CP_WAIT0()  asm volatile("cp.async.wait_group 0;" ::: "memory")

// ---------------- 1) query L2 normalize + bf16 copy ----------------
__global__ void qnorm_kernel(const float* __restrict__ q) {
    int b = blockIdx.x;
    const float* row = q + (size_t)b * FEAT;
    float s = 0.f;
    for (int i = threadIdx.x; i < FEAT; i += blockDim.x) { float v = row[i]; s += v * v; }
    __shared__ float red[32];
    int lane = threadIdx.x & 31, wid = threadIdx.x >> 5;
    #pragma unroll
    for (int o = 16; o > 0; o >>= 1) s += __shfl_xor_sync(0xFFFFFFFFu, s, o);
    if (lane == 0) red[wid] = s;
    __syncthreads();
    if (wid == 0) {
        s = (lane < (int)(blockDim.x >> 5)) ? red[lane] : 0.f;
        #pragma unroll
        for (int o = 16; o > 0; o >>= 1) s += __shfl_xor_sync(0xFFFFFFFFu, s, o);
        if (lane == 0) red[0] = s;
    }
    __syncthreads();
    float inv = 1.0f / sqrtf(red[0]);
    for (int i = threadIdx.x; i < FEAT; i += blockDim.x) {
        float v = row[i] * inv;
        g_qn[(size_t)b * FEAT + i] = v;
        g_qbf[(size_t)b * FEAT + i] = __float2bfloat16(v);
    }
}

// ---------------- 2) bf16 mma.sync score GEMM ----------------
// C[128 batch, MEM keys]; block tile 128x128, K chunks of 64, both A and B
// double-buffered (4 x 16KB = 64KB smem) -> 2 CTAs/SM.
#define BK 64
#define A_TILE 16384
#define B_TILE 16384
#define GEMM_SMEM (2 * A_TILE + 2 * B_TILE)   // 64 KB

__global__ __launch_bounds__(256, 2) void score_gemm_mma(const float* __restrict__ sk) {
    extern __shared__ __align__(1024) char smem[];
    const int tid = threadIdx.x;
    const int wid = tid >> 5, lane = tid & 31;
    const int wm = (wid & 1) * 64;          // warp M offset (batch rows)
    const int wn = (wid >> 1) * 32;         // warp N offset (keys)
    const int n0 = blockIdx.x * 128;
    const u32 sbase = smem_u32(smem);

    float acc[4][4][4];
    #pragma unroll
    for (int i = 0; i < 4; i++)
        #pragma unroll
        for (int j = 0; j < 4; j++)
            #pragma unroll
            for (int k = 0; k < 4; k++) acc[i][j][k] = 0.f;

    float4 st[4][2];   // B fp32 staging (one chunk)

    auto ldgB = [&](int c) {
        #pragma unroll
        for (int it = 0; it < 4; it++) {
            int id = tid + it * 256;
            int r = id >> 3, c32 = id & 7;
            const float4* p = reinterpret_cast<const float4*>(
                sk + (size_t)(n0 + r) * FEAT + c * BK + c32 * 8);
            st[it][0] = p[0]; st[it][1] = p[1];
        }
    };
    auto stsB = [&](int buf) {
        char* bb = smem + 2 * A_TILE + buf * B_TILE;
        #pragma unroll
        for (int it = 0; it < 4; it++) {
            int id = tid + it * 256;
            int r = id >> 3, c32 = id & 7;
            uint4 o;
            o.x = f2bf2(st[it][0].x, st[it][0].y);
            o.y = f2bf2(st[it][0].z, st[it][0].w);
            o.z = f2bf2(st[it][1].x, st[it][1].y);
            o.w = f2bf2(st[it][1].z, st[it][1].w);
            *reinterpret_cast<uint4*>(bb + swz(r * 128 + c32 * 16)) = o;
        }
    };
    auto cpA = [&](int c, int buf) {
        const char* src0 = reinterpret_cast<const char*>(g_qbf);
        u32 dst0 = sbase + buf * A_TILE;
        #pragma unroll
        for (int it = 0; it < 4; it++) {
            int id = tid + it * 256;
            int r = id >> 3, c16 = id & 7;
            cp_async16(dst0 + swz(r * 128 + c16 * 16),
                       src0 + r * 1024 + c * 128 + c16 * 16);
        }
    };

    const int jj = lane >> 3;
    const int akoff = (jj >= 2) ? 16 : 0;
    const int amoff = (jj & 1) * 8;
    const int bnoff = (jj >= 2) ? 8 : 0;
    const int bkoff = (jj & 1) * 16;
    auto compute = [&](int buf) {
        u32 abase = sbase + buf * A_TILE;
        u32 bbase = sbase + 2 * A_TILE + buf * B_TILE;
        #pragma unroll
        for (int ks = 0; ks < 4; ks++) {
            u32 a[4][4], b[2][4];
            #pragma unroll
            for (int mt = 0; mt < 4; mt++) {
                int arow = wm + mt * 16 + amoff + (lane & 7);
                ldsm_x4(a[mt], abase + arow * 128 + ((ks * 32 + akoff) ^ ((arow & 7) * 16)));
            }
            #pragma unroll
            for (int nt2 = 0; nt2 < 2; nt2++) {
                int brow = wn + nt2 * 16 + bnoff + (lane & 7);
                ldsm_x4(b[nt2], bbase + brow * 128 + ((ks * 32 + bkoff) ^ ((brow & 7) * 16)));
            }
            #pragma unroll
            for (int mt = 0; mt < 4; mt++)
                #pragma unroll
                for (int nt = 0; nt < 4; nt++)
                    mma16816(acc[mt][nt], a[mt], b[nt >> 1][(nt & 1) * 2],
                             b[nt >> 1][(nt & 1) * 2 + 1]);
        }
    };

    // ---- pipeline ----
    ldgB(0);
    cpA(0, 0);
    CP_COMMIT();
    CP_WAIT0();
    stsB(0);
    __syncthreads();
    for (int c = 0; c < FEAT / BK; c++) {
        int cur = c & 1;
        if (c < FEAT / BK - 1) { ldgB(c + 1); cpA(c + 1, cur ^ 1); CP_COMMIT(); }
        compute(cur);
        if (c < FEAT / BK - 1) { CP_WAIT0(); stsB(cur ^ 1); }
        __syncthreads();
    }

    // ---- epilogue: bf16 score stores (u32 = 2 bf16) ----
    #pragma unroll
    for (int mt = 0; mt < 4; mt++) {
        int r0 = wm + mt * 16 + (lane >> 2);
        #pragma unroll
        for (int nt = 0; nt < 4; nt++) {
            int col = n0 + wn + nt * 8 + (lane & 3) * 2;
            u32 w0 = f2bf2(acc[mt][nt][0], acc[mt][nt][1]);
            u32 w1 = f2bf2(acc[mt][nt][2], acc[mt][nt][3]);
            *reinterpret_cast<u32*>(&g_sbf[(size_t)r0 * MEM_SIZE + col]) = w0;
            *reinterpret_cast<u32*>(&g_sbf[(size_t)(r0 + 8) * MEM_SIZE + col]) = w1;
        }
    }
}

// ---------------- 3) candidate select on bf16 approx scores (uint4 loads) ----
__device__ __forceinline__ u32 fkey(float f) {
    u32 u = __float_as_uint(f);
    return (u & 0x80000000u) ? ~u : (u | 0x80000000u);
}

__global__ __launch_bounds__(1024) void cand_select() {
    int b = blockIdx.x;
    const uint4* row4 = reinterpret_cast<const uint4*>(g_sbf + (size_t)b * MEM_SIZE);
    __shared__ u32 hist[2048];
    __shared__ float s_thresh;
    for (int i = threadIdx.x; i < 2048; i += blockDim.x) hist[i] = 0;
    if (threadIdx.x == 0) g_cand_cnt[b] = 0;
    __syncthreads();

    // Pass 1: histogram (8 bf16 per uint4)
    for (int i = threadIdx.x; i < MEM_SIZE / 8; i += blockDim.x) {
        uint4 v = row4[i];
        u32 ws[4] = {v.x, v.y, v.z, v.w};
        #pragma unroll
        for (int j = 0; j < 4; j++) {
            float2 f = __bfloat1622float2(*reinterpret_cast<__nv_bfloat162*>(&ws[j]));
            atomicAdd(&hist[fkey(f.x) >> 21], 1);
            atomicAdd(&hist[fkey(f.y) >> 21], 1);
        }
    }
    __syncthreads();
    if (threadIdx.x == 0) {
        u32 cum = 0; int t = 0;
        for (int bin = 2047; bin >= 0; bin--) {
            cum += hist[bin];
            if (cum >= TOPK) { t = bin; break; }
        }
        u32 k = (u32)t << 21;
        float edge = (k & 0x80000000u) ? __uint_as_float(k ^ 0x80000000u)
                                       : __uint_as_float(~k);
        s_thresh = edge - 3.0e-3f;   // covers mma noise + bf16 storage rounding
    }
    __syncthreads();
    float th = s_thresh;

    // Pass 2: collect indices above threshold
    for (int i = threadIdx.x; i < MEM_SIZE / 8; i += blockDim.x) {
        uint4 v = row4[i];
        u32 ws[4] = {v.x, v.y, v.z, v.w};
        #pragma unroll
        for (int j = 0; j < 4; j++) {
            float2 f = __bfloat1622float2(*reinterpret_cast<__nv_bfloat162*>(&ws[j]));
            if (f.x > th) {
                int p = atomicAdd(&g_cand_cnt[b], 1);
                if (p < CAND_CAP) g_cand_idx[b * CAND_CAP + p] = i * 8 + j * 2;
            }
            if (f.y > th) {
                int p = atomicAdd(&g_cand_cnt[b], 1);
                if (p < CAND_CAP) g_cand_idx[b * CAND_CAP + p] = i * 8 + j * 2 + 1;
            }
        }
    }
}

// ---------------- 4) exact fp32 rescore (sequential-k order!) + exact rank ----
// CRITICAL: the dot product MUST accumulate in pure ascending-k order with a
// single fp32 fma chain — this exact order matches the reference ordering
// (R1/R5/R6 passed with it). Do not parallelize the reduction.
#define RES_SMEM (CAND_CAP * 8 + CAND_CAP * 4 + FEAT * 4)   // 51200 B

__global__ __launch_bounds__(1024) void rescore_rank(const float* __restrict__ sk,
                                                     float* __restrict__ out_score,
                                                     float* __restrict__ out_index) {
    int b = blockIdx.x;
    extern __shared__ __align__(16) char rsm[];
    u64*   s_key = reinterpret_cast<u64*>(rsm);
    float* s_sc  = reinterpret_cast<float*>(rsm + CAND_CAP * 8);
    float* s_q   = reinterpret_cast<float*>(rsm + CAND_CAP * 12);
    for (int i = threadIdx.x; i < FEAT; i += blockDim.x) s_q[i] = g_qn[(size_t)b * FEAT + i];
    __syncthreads();

    int n = g_cand_cnt[b];
    if (n > CAND_CAP) n = CAND_CAP;
    const float4* q4 = reinterpret_cast<const float4*>(s_q);
    for (int ci = threadIdx.x; ci < n; ci += blockDim.x) {
        int idx = g_cand_idx[b * CAND_CAP + ci];
        const float4* kr = reinterpret_cast<const float4*>(sk + (size_t)idx * FEAT);
        float acc = 0.f;
        #pragma unroll 8
        for (int j = 0; j < FEAT / 4; j++) {
            float4 kv = kr[j];
            float4 qv = q4[j];
            acc = fmaf(qv.x, kv.x, acc);
            acc = fmaf(qv.y, kv.y, acc);
            acc = fmaf(qv.z, kv.z, acc);
            acc = fmaf(qv.w, kv.w, acc);
        }
        s_sc[ci] = acc;
        s_key[ci] = ((u64)fkey(acc) << 32) | (u32)(0xFFFFFFFFu - (u32)idx);
    }
    __syncthreads();
    for (int ci = threadIdx.x; ci < n; ci += blockDim.x) {
        u64 kc = s_key[ci];
        int rank = 0;
        for (int j = 0; j < n; j++) rank += (s_key[j] > kc);
        if (rank < TOPK) {
            int idx = (int)(0xFFFFFFFFu - (u32)(kc & 0xFFFFFFFFull));
            out_score[b * TOPK + rank] = s_sc[ci];
            out_index[b * TOPK + rank] = (float)idx;
            g_topk_idx[b * TOPK + rank] = idx;
        }
    }
}

// ---------------- 5) gather ----------------
__global__ void gather_kernel(const float* __restrict__ cv, float* __restrict__ out_feat) {
    int r = blockIdx.x;
    int idx = g_topk_idx[r];
    const float4* src = reinterpret_cast<const float4*>(cv + (size_t)idx * FEAT);
    float4* dst = reinterpret_cast<float4*>(out_feat + (size_t)r * FEAT);
    dst[threadIdx.x] = src[threadIdx.x];
}

// ---------------- launch ----------------
extern "C" void kernel_launch(void* const* d_in, const int* in_sizes, int n_in,
                              void* d_out, int out_size) {
    const float* query = (const float*)d_in[0];
    const float* skey  = (const float*)d_in[1];
    const float* cval  = (const float*)d_in[2];
    float* out = (float*)d_out;
    float* out_feat  = out;
    float* out_score = out + (size_t)BATCH * TOPK * FEAT;
    float* out_index = out_score + (size_t)BATCH * TOPK;

    cudaFuncSetAttribute(score_gemm_mma, cudaFuncAttributeMaxDynamicSharedMemorySize, GEMM_SMEM);
    cudaFuncSetAttribute(rescore_rank, cudaFuncAttributeMaxDynamicSharedMemorySize, RES_SMEM);

    qnorm_kernel<<<BATCH, 128>>>(query);
    score_gemm_mma<<<MEM_SIZE / 128, 256, GEMM_SMEM>>>(skey);
    cand_select<<<BATCH, 1024>>>();
    rescore_rank<<<BATCH, 1024, RES_SMEM>>>(skey, out_score, out_index);
    gather_kernel<<<BATCH * TOPK, 128>>>(cval, out_feat);
}